// round 11
// baseline (speedup 1.0000x reference)
#include <cuda_runtime.h>

#define NT    256
#define GRID  1184                 // 148 SMs x 8 blocks: exactly one wave
#define STRIDE (GRID * NT)

__device__ double       g_acc;
__device__ unsigned int g_cnt;

__device__ __forceinline__ float frcp(float x) {
    float r; asm("rcp.approx.f32 %0, %1;" : "=f"(r) : "f"(x)); return r;
}

__device__ __forceinline__ float pair_loss(const float* __restrict__ p,
                                           const float* __restrict__ q) {
    float x1 = p[0], y1 = p[1], w1 = p[2], h1 = p[3], a1 = p[4];
    float x2 = q[0], y2 = q[1], w2 = q[2], h2 = q[3], a2 = q[4];

    // Box2 local frame, affine-normalized: clip region = [0,1]^2.
    float sf, cf, s2, c2;
    __sincosf(a1 - a2, &sf, &cf);
    __sincosf(a2, &s2, &c2);
    float ddx = x1 - x2, ddy = y1 - y2;
    float dxl = fmaf(ddx, c2, ddy * s2);
    float dyl = fmaf(-ddx, s2, ddy * c2);

    float iw = frcp(w2), ih = frcp(h2);
    float du = fmaf(dxl, iw, 0.5f);
    float dv = fmaf(dyl, ih, 0.5f);
    float hw1 = 0.5f * w1, hh1 = 0.5f * h1;
    float uxn = (hw1 * cf) * iw, uyn = (hw1 * sf) * ih;
    float vxn = -(hh1 * sf) * iw, vyn = (hh1 * cf) * ih;

    // Parallelogram corners and edge vectors (edges are +/-2u, +/-2v).
    float Pu[4], Pv[4];
    Pu[0] = du - uxn - vxn; Pv[0] = dv - uyn - vyn;
    Pu[1] = du + uxn - vxn; Pv[1] = dv + uyn - vyn;
    Pu[2] = du + uxn + vxn; Pv[2] = dv + uyn + vyn;
    Pu[3] = du - uxn + vxn; Pv[3] = dv - uyn + vyn;
    float au = uxn + uxn, av = uyn + uyn;     // edge 0 dir; edge 2 = -this
    float bu = vxn + vxn, bv = vyn + vyn;     // edge 1 dir; edge 3 = -this
    float inv_a = frcp(au), inv_b = frcp(bu); // shared: rcp(-x) = -rcp(x)

    float acc = 0.0f, pxc = 0.0f, pyc = 0.0f, fxc = 0.0f, fyc = 0.0f;
    float F8u = 0.0f, F8v = 0.0f, p8u = 0.0f, p8v = 0.0f;

    #define EDGE2(cu_, cv_, nu_, nv_, FIRST)                               \
    {                                                                      \
        float ru = (nu_) - (cu_), rv = (nv_) - (cv_);                      \
        float inv = frcp(rv);                                              \
        float tl = __saturatef(-(cv_) * inv);                              \
        float th = __saturatef(fmaf(-(cv_), inv, inv));                    \
        float t0 = fminf(tl, th), t1 = fmaxf(tl, th);                      \
        float e0u = fmaf(t0, ru, (cu_));                                   \
        float e0v = __saturatef(fmaf(t0, rv, (cv_)));                      \
        float e1u = fmaf(t1, ru, (cu_));                                   \
        float e1v = __saturatef(fmaf(t1, rv, (cv_)));                      \
        if (FIRST) { fxc = e0u; fyc = e0v; }                               \
        else { acc = fmaf(pxc, e0v, acc); acc = fmaf(-pyc, e0u, acc); }    \
        acc = fmaf(e0u, e1v, acc);                                         \
        acc = fmaf(-e0v, e1u, acc);                                        \
        pxc = e1u; pyc = e1v;                                              \
    }

    // Pass 1 (u-clip to [0,1]) streamed into pass 2 (v-clip + shoelace).
    #pragma unroll
    for (int k = 0; k < 4; k++) {
        float cu = Pu[k], cv = Pv[k];
        float ru  = (k == 0) ? au : (k == 1) ? bu : (k == 2) ? -au : -bu;
        float rv  = (k == 0) ? av : (k == 1) ? bv : (k == 2) ? -av : -bv;
        float inv = (k == 0) ? inv_a : (k == 1) ? inv_b
                  : (k == 2) ? -inv_a : -inv_b;
        float tl = __saturatef(-cu * inv);
        float th = __saturatef(fmaf(-cu, inv, inv));
        float t0 = fminf(tl, th), t1 = fmaxf(tl, th);
        float v0u = __saturatef(fmaf(t0, ru, cu));
        float v0v = fmaf(t0, rv, cv);
        float v1u = __saturatef(fmaf(t1, ru, cu));
        float v1v = fmaf(t1, rv, cv);
        if (k == 0) {
            F8u = v0u; F8v = v0v;
            EDGE2(v0u, v0v, v1u, v1v, true);
        } else {
            EDGE2(p8u, p8v, v0u, v0v, false);
            EDGE2(v0u, v0v, v1u, v1v, false);
        }
        p8u = v1u; p8v = v1v;
    }
    EDGE2(p8u, p8v, F8u, F8v, false);      // close the 8-gon
    acc = fmaf(pxc, fyc, acc);             // close the 16-gon
    acc = fmaf(-pyc, fxc, acc);
    #undef EDGE2

    float A2 = w2 * h2;
    float area = 0.5f * fabsf(acc) * A2;   // un-normalize
    float A1 = w1 * h1;
    float iou = area / fmaxf(A1 + A2 - area, 1e-10f);
    return -__logf(fmaxf(iou, 1e-6f));
}

__global__ void __launch_bounds__(NT, 8)
k_loss(const float* __restrict__ pred, const float* __restrict__ tgt,
       float* __restrict__ out, int n) {
    __shared__ double ssum[NT / 32];

    const int tid = threadIdx.x;
    float loss = 0.0f;
    #pragma unroll 1
    for (int i = blockIdx.x * NT + tid; i < n; i += STRIDE)
        loss += pair_loss(pred + (size_t)i * 5, tgt + (size_t)i * 5);

    // ---- block reduction ----
    #pragma unroll
    for (int o = 16; o > 0; o >>= 1)
        loss += __shfl_down_sync(0xFFFFFFFFu, loss, o);
    int lane = tid & 31, warp = tid >> 5;
    if (lane == 0) ssum[warp] = (double)loss;
    __syncthreads();

    if (tid == 0) {
        double t = 0.0;
        #pragma unroll
        for (int w = 0; w < NT / 32; w++) t += ssum[w];
        atomicAdd(&g_acc, t);
        __threadfence();
        unsigned int done = atomicAdd(&g_cnt, 1u);
        if (done == (unsigned int)(GRID - 1)) {
            double a = atomicAdd(&g_acc, 0.0);
            out[0] = (float)(a / (double)n);
            atomicExch((unsigned long long*)&g_acc, 0ull);
            atomicExch(&g_cnt, 0u);
        }
    }
}

extern "C" void kernel_launch(void* const* d_in, const int* in_sizes, int n_in,
                              void* d_out, int out_size) {
    const float* pred = (const float*)d_in[0];
    const float* tgt  = (const float*)d_in[1];
    int n = in_sizes[0] / 5;
    k_loss<<<GRID, NT>>>(pred, tgt, (float*)d_out, n);
}

// round 12
// speedup vs baseline: 1.1750x; 1.1750x over previous
#include <cuda_runtime.h>

#define NT    256
#define GRID  888                  // 148 SMs x 6 blocks @ <=42 regs: one wave
#define STRIDE (GRID * NT)

__device__ double       g_acc;
__device__ unsigned int g_cnt;

__device__ __forceinline__ float frcp(float x) {
    float r; asm("rcp.approx.f32 %0, %1;" : "=f"(r) : "f"(x)); return r;
}

__device__ __forceinline__ float pair_loss(const float* __restrict__ p,
                                           const float* __restrict__ q) {
    float x1 = p[0], y1 = p[1], w1 = p[2], h1 = p[3], a1 = p[4];
    float x2 = q[0], y2 = q[1], w2 = q[2], h2 = q[3], a2 = q[4];

    // Box2 local frame, affine-normalized: clip region = [0,1]^2.
    float sf, cf, s2, c2;
    __sincosf(a1 - a2, &sf, &cf);
    __sincosf(a2, &s2, &c2);
    float ddx = x1 - x2, ddy = y1 - y2;
    float dxl = fmaf(ddx, c2, ddy * s2);
    float dyl = fmaf(-ddx, s2, ddy * c2);

    float iw = frcp(w2), ih = frcp(h2);
    float du = fmaf(dxl, iw, 0.5f);
    float dv = fmaf(dyl, ih, 0.5f);
    float hw1 = 0.5f * w1, hh1 = 0.5f * h1;
    float uxn = (hw1 * cf) * iw, uyn = (hw1 * sf) * ih;
    float vxn = -(hh1 * sf) * iw, vyn = (hh1 * cf) * ih;

    // Parallelogram corners; edges are +/-(2u), +/-(2v) with shared rcps.
    float Pu[4], Pv[4];
    Pu[0] = du - uxn - vxn; Pv[0] = dv - uyn - vyn;
    Pu[1] = du + uxn - vxn; Pv[1] = dv + uyn - vyn;
    Pu[2] = du + uxn + vxn; Pv[2] = dv + uyn + vyn;
    Pu[3] = du - uxn + vxn; Pv[3] = dv - uyn + vyn;
    float au = uxn + uxn, av = uyn + uyn;     // edge 0 dir; edge 2 = -this
    float bu = vxn + vxn, bv = vyn + vyn;     // edge 1 dir; edge 3 = -this
    float inv_a = frcp(au), inv_b = frcp(bu); // rcp(-x) = -rcp(x)

    float acc = 0.0f, pxc = 0.0f, pyc = 0.0f, fxc = 0.0f, fyc = 0.0f;
    float F8u = 0.0f, F8v = 0.0f, p8u = 0.0f, p8v = 0.0f;

    #define EDGE2(cu_, cv_, nu_, nv_, FIRST)                               \
    {                                                                      \
        float ru = (nu_) - (cu_), rv = (nv_) - (cv_);                      \
        float inv = frcp(rv);                                              \
        float tl = __saturatef(-(cv_) * inv);                              \
        float th = __saturatef(fmaf(-(cv_), inv, inv));                    \
        float t0 = fminf(tl, th), t1 = fmaxf(tl, th);                      \
        float e0u = fmaf(t0, ru, (cu_));                                   \
        float e0v = __saturatef(fmaf(t0, rv, (cv_)));                      \
        float e1u = fmaf(t1, ru, (cu_));                                   \
        float e1v = __saturatef(fmaf(t1, rv, (cv_)));                      \
        if (FIRST) { fxc = e0u; fyc = e0v; }                               \
        else { acc = fmaf(pxc, e0v, acc); acc = fmaf(-pyc, e0u, acc); }    \
        acc = fmaf(e0u, e1v, acc);                                         \
        acc = fmaf(-e0v, e1u, acc);                                        \
        pxc = e1u; pyc = e1v;                                              \
    }

    // Pass 1 (u-clip to [0,1]) streamed into pass 2 (v-clip + shoelace).
    #pragma unroll
    for (int k = 0; k < 4; k++) {
        float cu = Pu[k], cv = Pv[k];
        float ru  = (k == 0) ? au : (k == 1) ? bu : (k == 2) ? -au : -bu;
        float rv  = (k == 0) ? av : (k == 1) ? bv : (k == 2) ? -av : -bv;
        float inv = (k == 0) ? inv_a : (k == 1) ? inv_b
                  : (k == 2) ? -inv_a : -inv_b;
        float tl = __saturatef(-cu * inv);
        float th = __saturatef(fmaf(-cu, inv, inv));
        float t0 = fminf(tl, th), t1 = fmaxf(tl, th);
        float v0u = __saturatef(fmaf(t0, ru, cu));
        float v0v = fmaf(t0, rv, cv);
        float v1u = __saturatef(fmaf(t1, ru, cu));
        float v1v = fmaf(t1, rv, cv);
        if (k == 0) {
            F8u = v0u; F8v = v0v;
            EDGE2(v0u, v0v, v1u, v1v, true);
        } else {
            EDGE2(p8u, p8v, v0u, v0v, false);
            EDGE2(v0u, v0v, v1u, v1v, false);
        }
        p8u = v1u; p8v = v1v;
    }
    EDGE2(p8u, p8v, F8u, F8v, false);      // close the 8-gon
    acc = fmaf(pxc, fyc, acc);             // close the 16-gon
    acc = fmaf(-pyc, fxc, acc);
    #undef EDGE2

    float A2 = w2 * h2;
    float area = 0.5f * fabsf(acc) * A2;   // un-normalize
    float A1 = w1 * h1;
    float iou = area / fmaxf(A1 + A2 - area, 1e-10f);
    return -__logf(fmaxf(iou, 1e-6f));
}

__global__ void __launch_bounds__(NT)
k_loss(const float* __restrict__ pred, const float* __restrict__ tgt,
       float* __restrict__ out, int n) {
    __shared__ double ssum[NT / 32];

    const int tid = threadIdx.x;
    float loss = 0.0f;
    #pragma unroll 1
    for (int i = blockIdx.x * NT + tid; i < n; i += STRIDE)
        loss += pair_loss(pred + (size_t)i * 5, tgt + (size_t)i * 5);

    // ---- block reduction ----
    #pragma unroll
    for (int o = 16; o > 0; o >>= 1)
        loss += __shfl_down_sync(0xFFFFFFFFu, loss, o);
    int lane = tid & 31, warp = tid >> 5;
    if (lane == 0) ssum[warp] = (double)loss;
    __syncthreads();

    if (tid == 0) {
        double t = 0.0;
        #pragma unroll
        for (int w = 0; w < NT / 32; w++) t += ssum[w];
        atomicAdd(&g_acc, t);
        __threadfence();
        unsigned int done = atomicAdd(&g_cnt, 1u);
        if (done == (unsigned int)(GRID - 1)) {
            double a = atomicAdd(&g_acc, 0.0);
            out[0] = (float)(a / (double)n);
            atomicExch((unsigned long long*)&g_acc, 0ull);
            atomicExch(&g_cnt, 0u);
        }
    }
}

extern "C" void kernel_launch(void* const* d_in, const int* in_sizes, int n_in,
                              void* d_out, int out_size) {
    const float* pred = (const float*)d_in[0];
    const float* tgt  = (const float*)d_in[1];
    int n = in_sizes[0] / 5;
    k_loss<<<GRID, NT>>>(pred, tgt, (float*)d_out, n);
}

// round 13
// speedup vs baseline: 1.3988x; 1.1905x over previous
#include <cuda_runtime.h>

#define NT    256
#define GRID  888                  // 148 SMs x 6 blocks: one persistent wave
#define STRIDE (GRID * NT)

__device__ double       g_acc;
__device__ unsigned int g_cnt;

__device__ __forceinline__ float frcp(float x) {
    float r; asm("rcp.approx.f32 %0, %1;" : "=f"(r) : "f"(x)); return r;
}

__device__ __forceinline__ float pair_loss(const float* __restrict__ p,
                                           const float* __restrict__ q) {
    float x1 = p[0], y1 = p[1], w1 = p[2], h1 = p[3], a1 = p[4];
    float x2 = q[0], y2 = q[1], w2 = q[2], h2 = q[3], a2 = q[4];

    // Box2 local frame, affine-normalized: clip region = [0,1]^2.
    float sf, cf, s2, c2;
    __sincosf(a1 - a2, &sf, &cf);
    __sincosf(a2, &s2, &c2);
    float ddx = x1 - x2, ddy = y1 - y2;
    float dxl = fmaf(ddx, c2, ddy * s2);
    float dyl = fmaf(-ddx, s2, ddy * c2);

    float iw = frcp(w2), ih = frcp(h2);
    float du = fmaf(dxl, iw, 0.5f);
    float dv = fmaf(dyl, ih, 0.5f);
    float hw1 = 0.5f * w1, hh1 = 0.5f * h1;
    float uxn = (hw1 * cf) * iw, uyn = (hw1 * sf) * ih;
    float vxn = -(hh1 * sf) * iw, vyn = (hh1 * cf) * ih;

    // Parallelogram corners; edge dirs are +/-(2u), +/-(2v): 4 shared rcps.
    float Pu0 = du - uxn - vxn, Pv0 = dv - uyn - vyn;
    float Pu1 = du + uxn - vxn, Pv1 = dv + uyn - vyn;
    float Pu2 = du + uxn + vxn, Pv2 = dv + uyn + vyn;
    float Pu3 = du - uxn + vxn, Pv3 = dv - uyn + vyn;
    float au = uxn + uxn, av = uyn + uyn;
    float bu = vxn + vxn, bv = vyn + vyn;
    float iau = frcp(au), iav = frcp(av);
    float ibu = frcp(bu), ibv = frcp(bv);

    float acc0 = 0.0f, acc1 = 0.0f;
    float fu = 0.0f, fv = 0.0f, pu = 0.0f, pv = 0.0f;

    // Per original edge: u-window [t0,t1] and v-window [slo,shi] in the SAME
    // t-parameter (shared reciprocals). Emit 4 points: C0(t0), E0(tA), E1(tB),
    // C1(t1), all coordinate-saturated to [0,1]^2; connectors C1_k -> C0_{k+1}
    // are vertical boundary chords (rcp-free). Degenerate/empty windows
    // collapse to colinear-or-identical points: zero net shoelace area.
    #pragma unroll
    for (int k = 0; k < 4; k++) {
        float cu  = (k == 0) ? Pu0 : (k == 1) ? Pu1 : (k == 2) ? Pu2 : Pu3;
        float cv  = (k == 0) ? Pv0 : (k == 1) ? Pv1 : (k == 2) ? Pv2 : Pv3;
        float ru  = (k == 0) ? au  : (k == 1) ? bu  : (k == 2) ? -au : -bu;
        float rv  = (k == 0) ? av  : (k == 1) ? bv  : (k == 2) ? -av : -bv;
        float iru = (k == 0) ? iau : (k == 1) ? ibu : (k == 2) ? -iau : -ibu;
        float irv = (k == 0) ? iav : (k == 1) ? ibv : (k == 2) ? -iav : -ibv;

        float tl = __saturatef(-cu * iru);
        float th = __saturatef(fmaf(-cu, iru, iru));
        float t0 = fminf(tl, th), t1 = fmaxf(tl, th);

        float sv0 = -cv * irv;
        float sv1 = fmaf(-cv, irv, irv);
        float slo = fminf(sv0, sv1), shi = fmaxf(sv0, sv1);

        float tA = fmaxf(t0, slo);
        float tB = fmaxf(fminf(t1, shi), tA);

        float Au = __saturatef(fmaf(t0, ru, cu)), Av = __saturatef(fmaf(t0, rv, cv));
        float Bu = __saturatef(fmaf(tA, ru, cu)), Bv = __saturatef(fmaf(tA, rv, cv));
        float Cu = __saturatef(fmaf(tB, ru, cu)), Cv = __saturatef(fmaf(tB, rv, cv));
        float Du = __saturatef(fmaf(t1, ru, cu)), Dv = __saturatef(fmaf(t1, rv, cv));

        if (k == 0) { fu = Au; fv = Av; }
        else { acc0 = fmaf(pu, Av, acc0); acc0 = fmaf(-pv, Au, acc0); }
        acc1 = fmaf(Au, Bv, acc1); acc1 = fmaf(-Av, Bu, acc1);
        acc0 = fmaf(Bu, Cv, acc0); acc0 = fmaf(-Bv, Cu, acc0);
        acc1 = fmaf(Cu, Dv, acc1); acc1 = fmaf(-Cv, Du, acc1);
        pu = Du; pv = Dv;
    }
    acc0 = fmaf(pu, fv, acc0);
    acc0 = fmaf(-pv, fu, acc0);

    float A2 = w2 * h2, A1 = w1 * h1;
    float area = 0.5f * fabsf(acc0 + acc1) * A2;   // un-normalize
    float den = fmaxf(A1 + A2 - area, 1e-10f);
    // -log(clip(area/den, 1e-6)) == min(log(den)-log(area), -log(1e-6))
    float loss = __logf(den) - __logf(area);
    return fminf(loss, 13.815511f);
}

__global__ void __launch_bounds__(NT)
k_loss(const float* __restrict__ pred, const float* __restrict__ tgt,
       float* __restrict__ out, int n) {
    __shared__ double ssum[NT / 32];

    const int tid = threadIdx.x;
    float loss = 0.0f;
    #pragma unroll 1
    for (int i = blockIdx.x * NT + tid; i < n; i += STRIDE)
        loss += pair_loss(pred + (size_t)i * 5, tgt + (size_t)i * 5);

    // ---- block reduction ----
    #pragma unroll
    for (int o = 16; o > 0; o >>= 1)
        loss += __shfl_down_sync(0xFFFFFFFFu, loss, o);
    int lane = tid & 31, warp = tid >> 5;
    if (lane == 0) ssum[warp] = (double)loss;
    __syncthreads();

    if (tid == 0) {
        double t = 0.0;
        #pragma unroll
        for (int w = 0; w < NT / 32; w++) t += ssum[w];
        atomicAdd(&g_acc, t);
        __threadfence();
        unsigned int done = atomicAdd(&g_cnt, 1u);
        if (done == (unsigned int)(GRID - 1)) {
            double a = atomicAdd(&g_acc, 0.0);
            out[0] = (float)(a / (double)n);
            atomicExch((unsigned long long*)&g_acc, 0ull);
            atomicExch(&g_cnt, 0u);
        }
    }
}

extern "C" void kernel_launch(void* const* d_in, const int* in_sizes, int n_in,
                              void* d_out, int out_size) {
    const float* pred = (const float*)d_in[0];
    const float* tgt  = (const float*)d_in[1];
    int n = in_sizes[0] / 5;
    k_loss<<<GRID, NT>>>(pred, tgt, (float*)d_out, n);
}

// round 14
// speedup vs baseline: 1.4030x; 1.0030x over previous
#include <cuda_runtime.h>

#define NT    128
#define GRID  1184                 // 148 SMs x 8 blocks: single persistent wave
#define STRIDE (GRID * NT)

__device__ double       g_acc;
__device__ unsigned int g_cnt;

__device__ __forceinline__ float frcp(float x) {
    float r; asm("rcp.approx.f32 %0, %1;" : "=f"(r) : "f"(x)); return r;
}

// Compute loss for one pair given its 10 raw values in registers.
__device__ __forceinline__ float pair_loss(const float* b) {
    float x1 = b[0], y1 = b[1], w1 = b[2], h1 = b[3], a1 = b[4];
    float x2 = b[5], y2 = b[6], w2 = b[7], h2 = b[8], a2 = b[9];

    // Box2 local frame, affine-normalized: clip region = [0,1]^2.
    float sf, cf, s2, c2;
    __sincosf(a1 - a2, &sf, &cf);
    __sincosf(a2, &s2, &c2);
    float ddx = x1 - x2, ddy = y1 - y2;
    float dxl = fmaf(ddx, c2, ddy * s2);
    float dyl = fmaf(-ddx, s2, ddy * c2);

    float iw = frcp(w2), ih = frcp(h2);
    float du = fmaf(dxl, iw, 0.5f);
    float dv = fmaf(dyl, ih, 0.5f);
    float hw1 = 0.5f * w1, hh1 = 0.5f * h1;
    float uxn = (hw1 * cf) * iw, uyn = (hw1 * sf) * ih;
    float vxn = -(hh1 * sf) * iw, vyn = (hh1 * cf) * ih;

    float Pu0 = du - uxn - vxn, Pv0 = dv - uyn - vyn;
    float Pu1 = du + uxn - vxn, Pv1 = dv + uyn - vyn;
    float Pu2 = du + uxn + vxn, Pv2 = dv + uyn + vyn;
    float Pu3 = du - uxn + vxn, Pv3 = dv - uyn + vyn;
    float au = uxn + uxn, av = uyn + uyn;
    float bu = vxn + vxn, bv = vyn + vyn;
    float iau = frcp(au), iav = frcp(av);
    float ibu = frcp(bu), ibv = frcp(bv);

    float acc0 = 0.0f, acc1 = 0.0f;
    float fu = 0.0f, fv = 0.0f, pu = 0.0f, pv = 0.0f;

    // Per original edge: u-window [t0,t1] and v-window [slo,shi] in the same
    // t-parameter (shared reciprocals); 4 saturated emission points; connector
    // chords are boundary segments (zero net area on degeneracy).
    #pragma unroll
    for (int k = 0; k < 4; k++) {
        float cu  = (k == 0) ? Pu0 : (k == 1) ? Pu1 : (k == 2) ? Pu2 : Pu3;
        float cv  = (k == 0) ? Pv0 : (k == 1) ? Pv1 : (k == 2) ? Pv2 : Pv3;
        float ru  = (k == 0) ? au  : (k == 1) ? bu  : (k == 2) ? -au : -bu;
        float rv  = (k == 0) ? av  : (k == 1) ? bv  : (k == 2) ? -av : -bv;
        float iru = (k == 0) ? iau : (k == 1) ? ibu : (k == 2) ? -iau : -ibu;
        float irv = (k == 0) ? iav : (k == 1) ? ibv : (k == 2) ? -iav : -ibv;

        float tl = __saturatef(-cu * iru);
        float th = __saturatef(fmaf(-cu, iru, iru));
        float t0 = fminf(tl, th), t1 = fmaxf(tl, th);

        float sv0 = -cv * irv;
        float sv1 = fmaf(-cv, irv, irv);
        float slo = fminf(sv0, sv1), shi = fmaxf(sv0, sv1);

        float tA = fmaxf(t0, slo);
        float tB = fmaxf(fminf(t1, shi), tA);

        float Au = __saturatef(fmaf(t0, ru, cu)), Av = __saturatef(fmaf(t0, rv, cv));
        float Bu = __saturatef(fmaf(tA, ru, cu)), Bv = __saturatef(fmaf(tA, rv, cv));
        float Cu = __saturatef(fmaf(tB, ru, cu)), Cv = __saturatef(fmaf(tB, rv, cv));
        float Du = __saturatef(fmaf(t1, ru, cu)), Dv = __saturatef(fmaf(t1, rv, cv));

        if (k == 0) { fu = Au; fv = Av; }
        else { acc0 = fmaf(pu, Av, acc0); acc0 = fmaf(-pv, Au, acc0); }
        acc1 = fmaf(Au, Bv, acc1); acc1 = fmaf(-Av, Bu, acc1);
        acc0 = fmaf(Bu, Cv, acc0); acc0 = fmaf(-Bv, Cu, acc0);
        acc1 = fmaf(Cu, Dv, acc1); acc1 = fmaf(-Cv, Du, acc1);
        pu = Du; pv = Dv;
    }
    acc0 = fmaf(pu, fv, acc0);
    acc0 = fmaf(-pv, fu, acc0);

    float A2 = w2 * h2, A1 = w1 * h1;
    float area = 0.5f * fabsf(acc0 + acc1) * A2;
    float den = fmaxf(A1 + A2 - area, 1e-10f);
    // -log(clip(area/den, 1e-6)) == min(log(den)-log(area), -log(1e-6))
    float loss = __logf(den) - __logf(area);
    return fminf(loss, 13.815511f);
}

__global__ void __launch_bounds__(NT)
k_loss(const float* __restrict__ pred, const float* __restrict__ tgt,
       float* __restrict__ out, int n) {
    __shared__ double ssum[NT / 32];

    const int tid = threadIdx.x;
    float loss = 0.0f;

    int i = blockIdx.x * NT + tid;
    if (i < n) {
        const float* pp = pred + (size_t)i * 5;
        const float* qq = tgt  + (size_t)i * 5;
        float b0[10];
        #pragma unroll
        for (int j = 0; j < 5; j++) { b0[j] = pp[j]; b0[5 + j] = qq[j]; }

        #pragma unroll 1
        for (;;) {
            int inext = i + STRIDE;
            bool more = inext < n;
            // Prefetch next pair's inputs while computing the current pair.
            float b1[10];
            if (more) {
                const float* pn = pp + (size_t)STRIDE * 5;
                const float* qn = qq + (size_t)STRIDE * 5;
                #pragma unroll
                for (int j = 0; j < 5; j++) { b1[j] = pn[j]; b1[5 + j] = qn[j]; }
            }
            loss += pair_loss(b0);
            if (!more) break;
            #pragma unroll
            for (int j = 0; j < 10; j++) b0[j] = b1[j];
            pp += (size_t)STRIDE * 5;
            qq += (size_t)STRIDE * 5;
            i = inext;
        }
    }

    // ---- block reduction ----
    #pragma unroll
    for (int o = 16; o > 0; o >>= 1)
        loss += __shfl_down_sync(0xFFFFFFFFu, loss, o);
    int lane = tid & 31, warp = tid >> 5;
    if (lane == 0) ssum[warp] = (double)loss;
    __syncthreads();

    if (tid == 0) {
        double t = 0.0;
        #pragma unroll
        for (int w = 0; w < NT / 32; w++) t += ssum[w];
        atomicAdd(&g_acc, t);
        __threadfence();
        unsigned int done = atomicAdd(&g_cnt, 1u);
        if (done == (unsigned int)(GRID - 1)) {
            double a = atomicAdd(&g_acc, 0.0);
            out[0] = (float)(a / (double)n);
            atomicExch((unsigned long long*)&g_acc, 0ull);
            atomicExch(&g_cnt, 0u);
        }
    }
}

extern "C" void kernel_launch(void* const* d_in, const int* in_sizes, int n_in,
                              void* d_out, int out_size) {
    const float* pred = (const float*)d_in[0];
    const float* tgt  = (const float*)d_in[1];
    int n = in_sizes[0] / 5;
    k_loss<<<GRID, NT>>>(pred, tgt, (float*)d_out, n);
}